// round 4
// baseline (speedup 1.0000x reference)
#include <cuda_runtime.h>
#include <mma.h>

using namespace nvcuda;

#define PATCH 7
#define PP (PATCH * PATCH)

// Scratch for MLP ping-pong (no cudaMalloc allowed). Sized for up to 2048 queries x 256 dim.
__device__ float g_buf0[2048 * 256];
__device__ float g_buf1[2048 * 256];

__device__ __forceinline__ float to_tf32(float x) {
    float r;
    asm("cvt.rna.tf32.f32 %0, %1;" : "=f"(r) : "f"(x));
    return r;
}

// ---------------------------------------------------------------------------
// MLP layer via tf32x3 tensor-core GEMM.
// Y[M,N] = act(X[M,K] @ W[K,N] + bias[N]).
// Block: 32(M) x 32(N) tile, 128 threads = 4 warps, each warp one 16x16 wmma
// tile (m16n16k8, tf32). Grid (M/32, N/32) = (32, 8) = 256 blocks for
// M=1024,N=256 -> covers all 148 SMs.
// fp32 accuracy recovered via Dekker split: acc += ahi*bhi + ahi*blo + alo*bhi.
// ---------------------------------------------------------------------------
template <bool RELU>
__global__ void __launch_bounds__(128) mlp_tf32_kernel(
    const float* __restrict__ X, const float* __restrict__ W,
    const float* __restrict__ bias, float* __restrict__ Y,
    int M, int K, int N)
{
    __shared__ float Cs[32][36];

    const int tid  = threadIdx.x;
    const int warp = tid >> 5;
    const int bm = blockIdx.x * 32;
    const int bn = blockIdx.y * 32;
    const int wm = bm + (warp >> 1) * 16;   // warp row origin
    const int wn = bn + (warp & 1) * 16;    // warp col origin

    wmma::fragment<wmma::accumulator, 16, 16, 8, float> acc;
    wmma::fill_fragment(acc, 0.0f);

    wmma::fragment<wmma::matrix_a, 16, 16, 8, wmma::precision::tf32, wmma::row_major> a_raw, a_hi, a_lo;
    wmma::fragment<wmma::matrix_b, 16, 16, 8, wmma::precision::tf32, wmma::row_major> b_raw, b_hi, b_lo;

    for (int k0 = 0; k0 < K; k0 += 8) {
        wmma::load_matrix_sync(a_raw, X + (size_t)wm * K + k0, K);
        wmma::load_matrix_sync(b_raw, W + (size_t)k0 * N + wn, N);

#pragma unroll
        for (int i = 0; i < a_raw.num_elements; i++) {
            float v  = a_raw.x[i];
            float hi = to_tf32(v);
            a_hi.x[i] = hi;
            a_lo.x[i] = to_tf32(v - hi);
        }
#pragma unroll
        for (int i = 0; i < b_raw.num_elements; i++) {
            float v  = b_raw.x[i];
            float hi = to_tf32(v);
            b_hi.x[i] = hi;
            b_lo.x[i] = to_tf32(v - hi);
        }

        wmma::mma_sync(acc, a_hi, b_hi, acc);
        wmma::mma_sync(acc, a_hi, b_lo, acc);
        wmma::mma_sync(acc, a_lo, b_hi, acc);
    }

    wmma::store_matrix_sync(&Cs[(warp >> 1) * 16][(warp & 1) * 16], acc, 36,
                            wmma::mem_row_major);
    __syncthreads();

    // Coalesced write-out with bias + activation. 32 rows x 8 float4 = 256.
    for (int idx = tid; idx < 256; idx += 128) {
        int r  = idx >> 3;          // 0..31
        int c4 = (idx & 7) << 2;    // 0,4,...,28
        float4 v  = *reinterpret_cast<float4*>(&Cs[r][c4]);
        float4 bb = *reinterpret_cast<const float4*>(&bias[bn + c4]);
        v.x += bb.x; v.y += bb.y; v.z += bb.z; v.w += bb.w;
        if (RELU) {
            v.x = fmaxf(v.x, 0.f); v.y = fmaxf(v.y, 0.f);
            v.z = fmaxf(v.z, 0.f); v.w = fmaxf(v.w, 0.f);
        }
        *reinterpret_cast<float4*>(&Y[(size_t)(bm + r) * N + bn + c4]) = v;
    }
}

// ---------------------------------------------------------------------------
// Gather + dot + indices. One block per query, 256 threads (8 warps).
// Each warp handles patch pixels p = warp, warp+8, ... ; per pixel: contiguous
// 1KB feature row dotted with query embedding (in smem), warp-shuffle reduce.
// ---------------------------------------------------------------------------
__global__ void __launch_bounds__(256) gather_dot_kernel(
    const float* __restrict__ fmap,        // [B,H,W,D]
    const float* __restrict__ qe,          // [N,D]
    const float* __restrict__ qpos,        // [N,2] (x,y) normalized
    const int*   __restrict__ qoff,        // [B]
    const int*   __restrict__ shapes,      // [B,2]
    float* __restrict__ out_logits,        // [N,49]
    float* __restrict__ out_idx,           // [N,49,4] as float, may be null
    int B, int Q, int D)
{
    __shared__ float qe_s[512];
    __shared__ int meta[6]; // cy, cx, H, W, b, q_local

    const int q = blockIdx.x;
    const int tid = threadIdx.x;

    if (tid == 0) {
        int b = B - 1;
        while (b > 0 && q < qoff[b]) b--;
        int q_local = q - qoff[b];
        int Hs = shapes[2 * b + 0];
        int Ws = shapes[2 * b + 1];
        float px_f = qpos[2 * q + 0];
        float py_f = qpos[2 * q + 1];
        meta[0] = (int)(py_f * (float)Hs);   // truncation == astype(int32) for >=0
        meta[1] = (int)(px_f * (float)Ws);
        meta[2] = Hs;
        meta[3] = Ws;
        meta[4] = b;
        meta[5] = q_local;
    }
    for (int d = tid; d < D; d += blockDim.x) qe_s[d] = qe[(size_t)q * D + d];
    __syncthreads();

    const int cy = meta[0], cx = meta[1], H = meta[2], W = meta[3];
    const int b = meta[4], q_local = meta[5];
    const size_t base = (size_t)b * H * W * D;

    const int warp = tid >> 5;
    const int lane = tid & 31;
    const float4* qe4 = reinterpret_cast<const float4*>(qe_s);

    for (int p = warp; p < PP; p += 8) {
        const int i = p / PATCH;
        const int j = p % PATCH;
        int py = cy + i - PATCH / 2;
        int px = cx + j - PATCH / 2;
        py = min(max(py, 0), H - 1);
        px = min(max(px, 0), W - 1);

        const float4* row4 = reinterpret_cast<const float4*>(
            fmap + base + ((size_t)py * W + px) * D);

        float sum = 0.f;
        for (int d4 = lane; d4 * 4 < D; d4 += 32) {
            float4 f = row4[d4];
            float4 g = qe4[d4];
            sum += f.x * g.x + f.y * g.y + f.z * g.z + f.w * g.w;
        }
#pragma unroll
        for (int off = 16; off > 0; off >>= 1)
            sum += __shfl_down_sync(0xffffffffu, sum, off);

        if (lane == 0) out_logits[(size_t)q * PP + p] = sum;
        if (out_idx != nullptr && lane < 4) {
            int v = (lane == 0) ? b : (lane == 1) ? py : (lane == 2) ? px : q_local;
            out_idx[((size_t)q * PP + p) * 4 + lane] = (float)v;
        }
    }
}

// ---------------------------------------------------------------------------
extern "C" void kernel_launch(void* const* d_in, const int* in_sizes, int n_in,
                              void* d_out, int out_size)
{
    const float* fmap    = (const float*)d_in[0];
    const float* queries = (const float*)d_in[1];
    const float* qpos    = (const float*)d_in[2];
    const int*   qoff    = (const int*)d_in[3];
    const int*   shapes  = (const int*)d_in[4];
    const float* W0 = (const float*)d_in[5];
    const float* b0 = (const float*)d_in[6];
    const float* W1 = (const float*)d_in[7];
    const float* b1 = (const float*)d_in[8];
    const float* W2 = (const float*)d_in[9];
    const float* b2 = (const float*)d_in[10];
    const float* W3 = (const float*)d_in[11];
    const float* b3 = (const float*)d_in[12];

    const int D  = in_sizes[6];          // bias length
    const int Nq = in_sizes[1] / D;      // total queries
    const int B  = in_sizes[3];
    const int Q  = Nq / B;

    float* buf0 = nullptr;
    float* buf1 = nullptr;
    cudaGetSymbolAddress((void**)&buf0, g_buf0);
    cudaGetSymbolAddress((void**)&buf1, g_buf1);

    dim3 blk(128);
    dim3 grid(Nq / 32, D / 32);
    mlp_tf32_kernel<true ><<<grid, blk>>>(queries, W0, b0, buf0, Nq, D, D);
    mlp_tf32_kernel<true ><<<grid, blk>>>(buf0,    W1, b1, buf1, Nq, D, D);
    mlp_tf32_kernel<true ><<<grid, blk>>>(buf1,    W2, b2, buf0, Nq, D, D);
    mlp_tf32_kernel<false><<<grid, blk>>>(buf0,    W3, b3, buf1, Nq, D, D);

    float* logits = (float*)d_out;
    float* idxf = nullptr;
    if (out_size >= Nq * PP * 5) idxf = logits + (size_t)Nq * PP;

    gather_dot_kernel<<<Nq, 256>>>(fmap, buf1, qpos, qoff, shapes,
                                   logits, idxf, B, Q, D);
}